// round 14
// baseline (speedup 1.0000x reference)
#include <cuda_runtime.h>

// APLoss via split value-histogram + in-block suffix scan (2 kernels, no
// global state management):
//   s_ij = relu(1 - f_i + y_j)^2 ; T_i = f_i - 1 ; c_i = 1 - f_i
//   S_all[i] = sum_{y_j > T_i} (c_i+y_j)^2 = cnt*c^2 + 2c*Sy + Syy  (suffix)
//   S_pos[i] = same over j < npos (reference: y_true = [1]*npos + [0]*rest)
//   ua = 0.01*u_all[idx] + 0.99*S_all/N ; up likewise
//   loss = (1/(npos*N)) * sum_i (up*S_all/ua - S_pos)/ua
//
// kH: each element deposits (1, y, y^2) into pos bins (j<npos) or neg bins —
//     3 fp64 REDs/element, fire-and-forget. all-set = pos+neg at query time.
// kF: ONE block, 1024 threads, B=1024 bins (1 bin/thread/comp). Loads each
//     bin and immediately zeroes it (next-replay reset for free). Shuffle
//     suffix scan (2 barriers/comp), float suffixes in smem, 2048 queries
//     in-block (fp32 closed form — numerics validated in prior rounds),
//     block reduce, tid0 writes out. No atomic counters anywhere.
// Boundary-bin inclusion error <= (bin count ~100) * w^2 (w=1/64) ~ 2e-6 rel.

#define B     1024
#define LOV   (-8.0f)
#define INVW  64.0f             // B / 16
#define QMAX  16384
#define KFTH  1024

__device__ double g_bins[6][B];  // comps 0-2: neg (cnt,Sy,Syy); 3-5: pos

__device__ __forceinline__ int read_npos(const int* p, int n) {
    int v = p[0];
    if (v < 1) v = 1;
    if (v > n) v = n;
    if (v > QMAX) v = QMAX;
    return v;
}

__device__ __forceinline__ int binof(float v) {
    int b = (int)floorf((v - LOV) * INVW);
    return min(max(b, 0), B - 1);
}

// ---------------------------------------------------------------------------
// kH: split histogram. Bins are zero on entry (static init + kF reset).
// ---------------------------------------------------------------------------
__global__ void kH(const float* __restrict__ y_pred,
                   const int* __restrict__ d_npos, int n) {
    int j = blockIdx.x * blockDim.x + threadIdx.x;
    if (j >= n) return;
    int npos = read_npos(d_npos, n);
    float y = y_pred[j];
    int b = binof(y);
    double yd = (double)y;
    int base = (j < npos) ? 3 : 0;
    atomicAdd(&g_bins[base + 0][b], 1.0);
    atomicAdd(&g_bins[base + 1][b], yd);
    atomicAdd(&g_bins[base + 2][b], yd * yd);
}

// ---------------------------------------------------------------------------
// kF: suffix scan (in-block) + queries + output. Single block, 1024 threads.
// ---------------------------------------------------------------------------
__global__ __launch_bounds__(KFTH) void kF(
    const float* __restrict__ y_pred,
    const float* __restrict__ u_all,
    const float* __restrict__ u_pos,
    const int*   __restrict__ index_s,
    const int*   __restrict__ d_npos,
    float* __restrict__ out, int n)
{
    __shared__ float  sSuf[6][B];   // 24 KB suffix tables
    __shared__ double sW[32];
    __shared__ double sT[32];
    __shared__ double sR[32];

    const int tid  = threadIdx.x;
    const int lane = tid & 31;
    const int wid  = tid >> 5;

    const int npos = read_npos(d_npos, n);   // issued early, used later

    // ---- suffix scan, one component at a time (1 bin per thread) ----
    for (int comp = 0; comp < 6; comp++) {
        double v = g_bins[comp][tid];
        g_bins[comp][tid] = 0.0;              // reset for next graph replay

        // warp inclusive suffix scan
        double s = v;
        #pragma unroll
        for (int off = 1; off < 32; off <<= 1) {
            double o = __shfl_down_sync(0xffffffffu, s, off);
            if (lane + off < 32) s += o;
        }
        if (lane == 0) sW[wid] = s;           // warp totals
        __syncthreads();
        if (wid == 0) {                       // scan the 32 warp totals
            double ss = sW[lane];
            #pragma unroll
            for (int off = 1; off < 32; off <<= 1) {
                double o = __shfl_down_sync(0xffffffffu, ss, off);
                if (lane + off < 32) ss += o;
            }
            double tl = __shfl_down_sync(0xffffffffu, ss, 1);
            if (lane == 31) tl = 0.0;
            sT[lane] = tl;                    // suffix of LATER warps
        }
        __syncthreads();
        sSuf[comp][tid] = (float)(s + sT[wid]);
    }
    __syncthreads();

    // ---- queries: closed form per positive anchor (fp32, validated) ----
    const float G    = 0.99f;
    const float OMG  = 1.0f - 0.99f;
    const float invN = 1.0f / (float)n;

    double acc = 0.0;
    for (int q = tid; q < npos; q += KFTH) {
        float f = y_pred[q];
        int b = binof(f - 1.0f);              // bin of threshold T = f-1
        float nc  = sSuf[0][b], nSy  = sSuf[1][b], nSyy  = sSuf[2][b];
        float pc  = sSuf[3][b], pSy  = sSuf[4][b], pSyy  = sSuf[5][b];
        double c = 1.0 - (double)f;
        double S_all = ((double)(nc + pc) * c + 2.0 * (double)(nSy + pSy)) * c
                       + (double)(nSyy + pSyy);
        double S_pos = ((double)pc * c + 2.0 * (double)pSy) * c + (double)pSyy;
        float Sa = (float)S_all;
        float Sp = (float)S_pos;
        int id = index_s[q];
        float ua = OMG * u_all[id] + G * (Sa * invN);
        float up = OMG * u_pos[id] + G * (Sp * invN);
        float r  = 1.0f / ua;
        acc += (double)((up * Sa * r - Sp) * r);
    }

    // ---- block reduction + output ----
    #pragma unroll
    for (int off = 16; off > 0; off >>= 1)
        acc += __shfl_down_sync(0xffffffffu, acc, off);
    if (lane == 0) sR[wid] = acc;
    __syncthreads();
    if (tid == 0) {
        double L = 0.0;
        #pragma unroll
        for (int w = 0; w < 32; w++) L += sR[w];
        out[0] = (float)(L / ((double)npos * (double)n));
    }
}

// ---------------------------------------------------------------------------
extern "C" void kernel_launch(void* const* d_in, const int* in_sizes, int n_in,
                              void* d_out, int out_size) {
    const float* y_pred  = (const float*)d_in[0];
    const float* u_all   = (const float*)d_in[2];
    const float* u_pos   = (const float*)d_in[3];
    const int*   index_s = (const int*)  d_in[4];
    const int*   d_npos  = (const int*)  d_in[5];
    int n = in_sizes[0];

    int hb = (n + 127) / 128;
    kH<<<hb, 128>>>(y_pred, d_npos, n);
    kF<<<1, KFTH>>>(y_pred, u_all, u_pos, index_s, d_npos,
                    (float*)d_out, n);
}

// round 15
// speedup vs baseline: 1.4766x; 1.4766x over previous
#include <cuda_runtime.h>

// APLoss via split fp32 value-histogram + per-block redundant suffix scan.
//   s_ij = relu(1 - f_i + y_j)^2 ; T_i = f_i - 1 ; c_i = 1 - f_i
//   S_all[i] = sum_{y_j > T_i} (c_i+y_j)^2 = cnt*c^2 + 2c*Sy + Syy  (suffix)
//   S_pos[i] = same over j < npos (reference: y_true = [1]*npos + [0]*rest)
//   ua = 0.01*u_all[idx] + 0.99*S_all/N ; up likewise
//   loss = (1/(npos*N)) * sum_i (up*S_all/ua - S_pos)/ua
//
// kH: 3 fp32 REDs per element into pos (j<npos) or neg bins. fp32 REDG is the
//     fast native L2-atomic path; counts < 2^24 are exact in fp32.
// kQ: 64 blocks x 256. Each ACTIVE block redundantly suffix-scans all 6
//     components (warp w scans comp w; two-pass fp64 lane-suffix + shuffle
//     scan; one block barrier) into smem, then answers its 256 queries
//     (query operands prefetched before the scan). Exit ticket (R12-proven):
//     last block zeroes the bins for the next graph replay, writes out,
//     resets g_loss/g_done. NO single-block stage anywhere.
// Boundary-bin inclusion: per-pair err <= w^2 (w = 1/64) -> ~1e-6 relative.

#define B     1024
#define LOV   (-8.0f)
#define INVW  64.0f             // B / 16
#define QMAX  16384
#define NTH   256

__device__ float  g_bins[6][B];  // 0-2: neg (cnt,Sy,Syy); 3-5: pos
__device__ double g_loss;
__device__ int    g_done;

__device__ __forceinline__ int read_npos(const int* p, int n) {
    int v = p[0];
    if (v < 1) v = 1;
    if (v > n) v = n;
    if (v > QMAX) v = QMAX;
    return v;
}

__device__ __forceinline__ int binof(float v) {
    int b = (int)floorf((v - LOV) * INVW);
    return min(max(b, 0), B - 1);
}

// ---------------------------------------------------------------------------
// kH: split histogram, fp32 fire-and-forget REDs.
// Bins are zero on entry (static zero-init; kQ's last block re-zeroes).
// ---------------------------------------------------------------------------
__global__ void kH(const float* __restrict__ y_pred,
                   const int* __restrict__ d_npos, int n) {
    int j = blockIdx.x * NTH + threadIdx.x;
    if (j >= n) return;
    int npos = read_npos(d_npos, n);
    float y = y_pred[j];
    int b = binof(y);
    int base = (j < npos) ? 3 : 0;
    atomicAdd(&g_bins[base + 0][b], 1.0f);
    atomicAdd(&g_bins[base + 1][b], y);
    atomicAdd(&g_bins[base + 2][b], y * y);
}

// ---------------------------------------------------------------------------
// kQ: redundant per-block scan + 256 queries per block + ticket finalize.
// ---------------------------------------------------------------------------
__global__ __launch_bounds__(NTH) void kQ(
    const float* __restrict__ y_pred,
    const float* __restrict__ u_all,
    const float* __restrict__ u_pos,
    const int*   __restrict__ index_s,
    const int*   __restrict__ d_npos,
    float* __restrict__ out, int n)
{
    __shared__ float  sSuf[6][B];   // 24 KB suffix tables
    __shared__ double sR[NTH / 32];
    __shared__ int    sLast;

    const int tid  = threadIdx.x;
    const int lane = tid & 31;
    const int wid  = tid >> 5;
    const int q    = blockIdx.x * NTH + tid;
    const int q0   = blockIdx.x * NTH;

    const int npos = read_npos(d_npos, n);

    if (q0 < npos) {
        // ---- prefetch query operands (hide latency under the scan) ----
        const bool haveq = (q < npos);
        float f = 0.f, ua_in = 0.f, up_in = 0.f;
        if (haveq) {
            f = y_pred[q];
            int id = index_s[q];
            ua_in = u_all[id];
            up_in = u_pos[id];
        }

        // ---- suffix scan: warp w scans component w (lane owns 32 bins) ----
        if (wid < 6) {
            const float* bins = g_bins[wid];
            const int i0 = lane * 32;
            // pass 1: lane total
            double tot = 0.0;
            #pragma unroll
            for (int u = 0; u < 32; u++) tot += (double)bins[i0 + u];
            // warp inclusive suffix scan of lane totals
            double s = tot;
            #pragma unroll
            for (int off = 1; off < 32; off <<= 1) {
                double o = __shfl_down_sync(0xffffffffu, s, off);
                if (lane + off < 32) s += o;
            }
            double tail = __shfl_down_sync(0xffffffffu, s, 1);
            if (lane == 31) tail = 0.0;
            // pass 2: emit suffixes (bins L1-hot)
            double run = tail;
            float* dst = sSuf[wid];
            #pragma unroll
            for (int u = 31; u >= 0; u--) {
                run += (double)bins[i0 + u];
                dst[i0 + u] = (float)run;
            }
        }
        __syncthreads();

        // ---- query: closed form per positive anchor ----
        const float G    = 0.99f;
        const float OMG  = 1.0f - 0.99f;
        const float invN = 1.0f / (float)n;

        double term = 0.0;
        if (haveq) {
            int b = binof(f - 1.0f);            // bin of threshold T = f-1
            float nc  = sSuf[0][b], nSy = sSuf[1][b], nSyy = sSuf[2][b];
            float pc  = sSuf[3][b], pSy = sSuf[4][b], pSyy = sSuf[5][b];
            double c = 1.0 - (double)f;
            double S_all = ((double)(nc + pc) * c + 2.0 * (double)(nSy + pSy))
                           * c + (double)(nSyy + pSyy);
            double S_pos = ((double)pc * c + 2.0 * (double)pSy) * c
                           + (double)pSyy;
            float Sa = (float)S_all;
            float Sp = (float)S_pos;
            float ua = OMG * ua_in + G * (Sa * invN);
            float up = OMG * up_in + G * (Sp * invN);
            float r  = 1.0f / ua;
            term = (double)((up * Sa * r - Sp) * r);
        }
        #pragma unroll
        for (int off = 16; off > 0; off >>= 1)
            term += __shfl_down_sync(0xffffffffu, term, off);
        if (lane == 0) sR[wid] = term;
        __syncthreads();
        if (tid == 0) {
            double L = 0.0;
            #pragma unroll
            for (int w = 0; w < NTH / 32; w++) L += sR[w];
            atomicAdd(&g_loss, L);
        }
    }

    // ---- exit ticket: last block finalizes + resets everything ----
    __syncthreads();
    if (tid == 0) {
        __threadfence();                        // publish g_loss add / reads
        int old = atomicAdd(&g_done, 1);
        sLast = (old == (int)gridDim.x - 1) ? 1 : 0;
    }
    __syncthreads();
    if (sLast) {
        // all blocks have bumped -> no one reads g_bins anymore: zero them
        float* bf = &g_bins[0][0];
        for (int i = tid; i < 6 * B; i += NTH) bf[i] = 0.0f;
        if (tid == 0) {
            __threadfence();                    // acquire all g_loss adds
            double Lf = atomicAdd(&g_loss, 0.0);
            out[0] = (float)(Lf / ((double)npos * (double)n));
            atomicExch((unsigned long long*)&g_loss, 0ull);
            atomicExch(&g_done, 0);
            __threadfence();
        }
    }
}

// ---------------------------------------------------------------------------
extern "C" void kernel_launch(void* const* d_in, const int* in_sizes, int n_in,
                              void* d_out, int out_size) {
    const float* y_pred  = (const float*)d_in[0];
    const float* u_all   = (const float*)d_in[2];
    const float* u_pos   = (const float*)d_in[3];
    const int*   index_s = (const int*)  d_in[4];
    const int*   d_npos  = (const int*)  d_in[5];
    int n = in_sizes[0];

    int hb = (n + NTH - 1) / NTH;
    int qmax = (n < QMAX) ? n : QMAX;           // npos <= min(n, QMAX)
    int qb = (qmax + NTH - 1) / NTH;

    kH<<<hb, NTH>>>(y_pred, d_npos, n);
    kQ<<<qb, NTH>>>(y_pred, u_all, u_pos, index_s, d_npos,
                    (float*)d_out, n);
}

// round 16
// speedup vs baseline: 2.2636x; 1.5329x over previous
#include <cuda_runtime.h>

// APLoss via split fp32 value-histogram + parallel in-smem suffix scan.
//   s_ij = relu(1 - f_i + y_j)^2 ; T_i = f_i - 1 ; c_i = 1 - f_i
//   S_all[i] = sum_{y_j > T_i} (c_i+y_j)^2 = cnt*c^2 + 2c*Sy + Syy  (suffix)
//   S_pos[i] = same over j < npos (reference: y_true = [1]*npos + [0]*rest)
//   ua = 0.01*u_all[idx] + 0.99*S_all/N ; up likewise
//   loss = (1/(npos*N)) * sum_i (up*S_all/ua - S_pos)/ua
//
// kH: 3 fp32 REDs per element into pos (j<npos) or neg bins (native fast
//     L2-atomic path; counts < 2^24 exact in fp32).
// kQ: active blocks stage all 6x1024 bins to smem via coalesced float4 loads
//     (parallel, ONE L2 round-trip), then warp w suffix-scans component w
//     ENTIRELY in fp32 registers/shuffles (no fp64, no serial L2 chains),
//     then answers its 256 queries. Exit ticket: last block zeroes bins for
//     the next graph replay, writes out, resets counters (R15-proven).
// Boundary-bin inclusion: per-pair err <= w^2 (w=1/64) -> ~1e-6 relative.

#define B     1024
#define LOV   (-8.0f)
#define INVW  64.0f             // B / 16
#define QMAX  16384
#define NTH   256

__device__ __align__(16) float g_bins[6][B];  // 0-2: neg; 3-5: pos
__device__ double g_loss;
__device__ int    g_done;

__device__ __forceinline__ int read_npos(const int* p, int n) {
    int v = p[0];
    if (v < 1) v = 1;
    if (v > n) v = n;
    if (v > QMAX) v = QMAX;
    return v;
}

__device__ __forceinline__ int binof(float v) {
    int b = (int)floorf((v - LOV) * INVW);
    return min(max(b, 0), B - 1);
}

// ---------------------------------------------------------------------------
// kH: split histogram, fp32 fire-and-forget REDs.
// Bins are zero on entry (static zero-init; kQ's last block re-zeroes).
// ---------------------------------------------------------------------------
__global__ void kH(const float* __restrict__ y_pred,
                   const int* __restrict__ d_npos, int n) {
    int j = blockIdx.x * NTH + threadIdx.x;
    if (j >= n) return;
    int npos = read_npos(d_npos, n);
    float y = y_pred[j];
    int b = binof(y);
    int base = (j < npos) ? 3 : 0;
    atomicAdd(&g_bins[base + 0][b], 1.0f);
    atomicAdd(&g_bins[base + 1][b], y);
    atomicAdd(&g_bins[base + 2][b], y * y);
}

// ---------------------------------------------------------------------------
// kQ: parallel stage -> fp32 register scan -> queries -> ticket finalize.
// ---------------------------------------------------------------------------
__global__ __launch_bounds__(NTH) void kQ(
    const float* __restrict__ y_pred,
    const float* __restrict__ u_all,
    const float* __restrict__ u_pos,
    const int*   __restrict__ index_s,
    const int*   __restrict__ d_npos,
    float* __restrict__ out, int n)
{
    __shared__ __align__(16) float sSuf[6][B];    // 24 KB
    __shared__ double sR[NTH / 32];
    __shared__ int    sLast;

    const int tid  = threadIdx.x;
    const int lane = tid & 31;
    const int wid  = tid >> 5;
    const int q    = blockIdx.x * NTH + tid;
    const int q0   = blockIdx.x * NTH;

    const int npos = read_npos(d_npos, n);

    if (q0 < npos) {
        // ---- prefetch query operands (hide latency under stage+scan) ----
        const bool haveq = (q < npos);
        float f = 0.f, ua_in = 0.f, up_in = 0.f;
        if (haveq) {
            f = y_pred[q];
            int id = index_s[q];
            ua_in = u_all[id];
            up_in = u_pos[id];
        }

        // ---- stage bins -> smem: 1536 float4, coalesced, parallel ----
        {
            const float4* src = (const float4*)&g_bins[0][0];
            float4* dst = (float4*)&sSuf[0][0];
            #pragma unroll
            for (int i = 0; i < (6 * B / 4) / NTH; i++)   // 6 per thread
                dst[i * NTH + tid] = src[i * NTH + tid];
        }
        __syncthreads();

        // ---- suffix scan: warp w scans component w, all fp32, in regs ----
        if (wid < 6) {
            float* bins = sSuf[wid];
            const int i0 = lane * 32;
            float v[32];
            float tot = 0.f;
            #pragma unroll
            for (int u = 0; u < 32; u++) {      // LDS independent, adds 4cyc
                v[u] = bins[i0 + u];
                tot += v[u];
            }
            // warp inclusive suffix scan of lane totals (fp32 shuffles)
            float s = tot;
            #pragma unroll
            for (int off = 1; off < 32; off <<= 1) {
                float o = __shfl_down_sync(0xffffffffu, s, off);
                if (lane + off < 32) s += o;
            }
            float tail = __shfl_down_sync(0xffffffffu, s, 1);
            if (lane == 31) tail = 0.f;
            // emit suffixes back to smem (register chain, 4cyc/step)
            float run = tail;
            #pragma unroll
            for (int u = 31; u >= 0; u--) {
                run += v[u];
                bins[i0 + u] = run;
            }
        }
        __syncthreads();

        // ---- query: closed form per positive anchor ----
        const float G    = 0.99f;
        const float OMG  = 1.0f - 0.99f;
        const float invN = 1.0f / (float)n;

        double term = 0.0;
        if (haveq) {
            int b = binof(f - 1.0f);            // bin of threshold T = f-1
            float nc  = sSuf[0][b], nSy = sSuf[1][b], nSyy = sSuf[2][b];
            float pc  = sSuf[3][b], pSy = sSuf[4][b], pSyy = sSuf[5][b];
            double c = 1.0 - (double)f;
            double S_all = ((double)(nc + pc) * c + 2.0 * (double)(nSy + pSy))
                           * c + (double)(nSyy + pSyy);
            double S_pos = ((double)pc * c + 2.0 * (double)pSy) * c
                           + (double)pSyy;
            float Sa = (float)S_all;
            float Sp = (float)S_pos;
            float ua = OMG * ua_in + G * (Sa * invN);
            float up = OMG * up_in + G * (Sp * invN);
            float r  = 1.0f / ua;
            term = (double)((up * Sa * r - Sp) * r);
        }
        #pragma unroll
        for (int off = 16; off > 0; off >>= 1)
            term += __shfl_down_sync(0xffffffffu, term, off);
        if (lane == 0) sR[wid] = term;
        __syncthreads();
        if (tid == 0) {
            double L = 0.0;
            #pragma unroll
            for (int w = 0; w < NTH / 32; w++) L += sR[w];
            atomicAdd(&g_loss, L);
        }
    }

    // ---- exit ticket: last block finalizes + resets everything ----
    __syncthreads();
    if (tid == 0) {
        __threadfence();                        // publish g_loss add / reads
        int old = atomicAdd(&g_done, 1);
        sLast = (old == (int)gridDim.x - 1) ? 1 : 0;
    }
    __syncthreads();
    if (sLast) {
        // all blocks have bumped -> no one reads g_bins anymore: zero them
        float* bf = &g_bins[0][0];
        for (int i = tid; i < 6 * B; i += NTH) bf[i] = 0.0f;
        if (tid == 0) {
            __threadfence();                    // acquire all g_loss adds
            double Lf = atomicAdd(&g_loss, 0.0);
            out[0] = (float)(Lf / ((double)npos * (double)n));
            atomicExch((unsigned long long*)&g_loss, 0ull);
            atomicExch(&g_done, 0);
            __threadfence();
        }
    }
}

// ---------------------------------------------------------------------------
extern "C" void kernel_launch(void* const* d_in, const int* in_sizes, int n_in,
                              void* d_out, int out_size) {
    const float* y_pred  = (const float*)d_in[0];
    const float* u_all   = (const float*)d_in[2];
    const float* u_pos   = (const float*)d_in[3];
    const int*   index_s = (const int*)  d_in[4];
    const int*   d_npos  = (const int*)  d_in[5];
    int n = in_sizes[0];

    int hb = (n + NTH - 1) / NTH;
    int qmax = (n < QMAX) ? n : QMAX;           // npos <= min(n, QMAX)
    int qb = (qmax + NTH - 1) / NTH;

    kH<<<hb, NTH>>>(y_pred, d_npos, n);
    kQ<<<qb, NTH>>>(y_pred, u_all, u_pos, index_s, d_npos,
                    (float*)d_out, n);
}